// round 8
// baseline (speedup 1.0000x reference)
#include <cuda_runtime.h>
#include <cuda_fp16.h>
#include <cstdint>
#include <math.h>

#define BATCH 16
#define CIN   64
#define LEN   1024
#define HID   1024
#define OUTC  512
#define EPS   1e-5f
#define MTOT  (BATCH*LEN)   // 16384

// GEMM tiling: CTA 128x128, KC=16, 3-stage ring, single sync/iter, 2 CTAs/SM
#define KC     16
#define NK     (HID/KC)      // 64
#define A_ST   12288         // 3 A planes * 128 rows * 32B
#define B_ST   12288
#define STG    (A_ST + B_ST) // 24576
#define NSTG   3
#define SMEM_GEMM (NSTG*STG) // 73728

// fp32 SIMT proj tile params
#define GBM 128
#define GBN 128
#define GBK 16
#define GTM 8
#define GTN 8
#define NTHR 256

// ---------------- scratch ----------------
__device__ __align__(16)  float g_h1[MTOT*HID];
__device__ __align__(16)  float g_h2[MTOT*OUTC];
__device__ __align__(128) __half g_A3a[(size_t)MTOT*3072];   // [m][order(3)][k]
__device__ __align__(128) __half g_A3b[(size_t)MTOT*3072];
__device__ __align__(128) __half g_B3a[(size_t)3*HID*1024];  // [order][n][k]
__device__ __align__(128) __half g_B3b[(size_t)3*OUTC*1024];
__device__ float g_c01[HID];
__device__ float g_c02[OUTC];
__device__ float g_part[BATCH*8*OUTC];

// ---------------- helpers ----------------
__device__ __forceinline__ uint32_t smem_u32(const void* p) {
    uint32_t a;
    asm("{ .reg .u64 t; cvta.to.shared.u64 t, %1; cvt.u32.u64 %0, t; }" : "=r"(a) : "l"(p));
    return a;
}

#define LDSM_X4(r, addr) \
    asm volatile("ldmatrix.sync.aligned.m8n8.x4.shared.b16 {%0,%1,%2,%3}, [%4];" \
        : "=r"((r)[0]), "=r"((r)[1]), "=r"((r)[2]), "=r"((r)[3]) : "r"(addr))
#define LDSM_X2(r, addr) \
    asm volatile("ldmatrix.sync.aligned.m8n8.x2.shared.b16 {%0,%1}, [%2];" \
        : "=r"((r)[0]), "=r"((r)[1]) : "r"(addr))
#define MMA16816(d, a, b) \
    asm volatile("mma.sync.aligned.m16n8k16.row.col.f32.f16.f16.f32 " \
        "{%0,%1,%2,%3}, {%4,%5,%6,%7}, {%8,%9}, {%0,%1,%2,%3};" \
        : "+f"((d)[0]), "+f"((d)[1]), "+f"((d)[2]), "+f"((d)[3]) \
        : "r"((a)[0]), "r"((a)[1]), "r"((a)[2]), "r"((a)[3]), "r"((b)[0]), "r"((b)[1]))

// ---------------- B repack (single fp16 plane per order) + c0 ----------------
template<int STAGE>
__global__ void repackB_kernel(const float* __restrict__ coeffs, const float* __restrict__ bias) {
    const int N = (STAGE == 1) ? HID : OUTC;
    __half* B3 = (STAGE == 1) ? g_B3a : g_B3b;
    float* c0  = (STAGE == 1) ? g_c01 : g_c02;
    int o = blockIdx.x;
    __shared__ float red[256];
    float s = 0.f;
    #pragma unroll
    for (int it = 0; it < 4; it++) {
        int c = threadIdx.x + it * 256;
        float4 v = *reinterpret_cast<const float4*>(coeffs + ((size_t)o * HID + c) * 4);
        s += v.x;
        size_t base = (size_t)o * 1024 + c;
        size_t ps = (size_t)N * 1024;
        B3[0*ps + base] = __float2half_rn(v.y);
        B3[1*ps + base] = __float2half_rn(v.z);
        B3[2*ps + base] = __float2half_rn(v.w);
    }
    red[threadIdx.x] = s; __syncthreads();
    #pragma unroll
    for (int st = 128; st > 0; st >>= 1) {
        if (threadIdx.x < st) red[threadIdx.x] += red[threadIdx.x + st];
        __syncthreads();
    }
    if (threadIdx.x == 0) c0[o] = red[0] + bias[o];
}

// ---------------- projection GEMM (fp32 SIMT) + fused power split to fp16 ----------------
__global__ void gemm_proj_kernel(const float* __restrict__ x, const float* __restrict__ W,
                                 const float* __restrict__ bias) {
    __shared__ float As[GBK][GBM];
    __shared__ float Bs[GBK][GBN];
    const int m0 = blockIdx.y * GBM, n0 = blockIdx.x * GBN;
    const int tid = threadIdx.x;
    const int tx = tid & 15, ty = tid >> 4;
    float acc[GTM][GTN] = {};
    for (int kt = 0; kt < CIN; kt += GBK) {
        #pragma unroll
        for (int ii = 0; ii < 8; ii++) {
            int idx = tid + ii * NTHR;
            int mm = idx & (GBM - 1);
            int kk = idx >> 7;
            int m = m0 + mm;
            As[kk][mm] = x[((size_t)(m >> 10) * CIN + (kt + kk)) * LEN + (m & 1023)];
        }
        #pragma unroll
        for (int ii = 0; ii < 8; ii++) {
            int idx = tid + ii * NTHR;
            int nn = idx & (GBN - 1);
            int kk = idx >> 7;
            Bs[kk][nn] = W[(size_t)(kt + kk) * HID + n0 + nn];
        }
        __syncthreads();
        #pragma unroll
        for (int kk = 0; kk < GBK; kk++) {
            float a[GTM], bb[GTN];
            #pragma unroll
            for (int i = 0; i < GTM; i++) a[i] = As[kk][ty * GTM + i];
            #pragma unroll
            for (int j = 0; j < GTN; j++) bb[j] = Bs[kk][tx * GTN + j];
            #pragma unroll
            for (int i = 0; i < GTM; i++)
                #pragma unroll
                for (int j = 0; j < GTN; j++)
                    acc[i][j] = fmaf(a[i], bb[j], acc[i][j]);
        }
        __syncthreads();
    }
    float bv[GTN];
    #pragma unroll
    for (int j = 0; j < GTN; j++) bv[j] = bias[n0 + tx * GTN + j];
    #pragma unroll
    for (int i = 0; i < GTM; i++) {
        int m = m0 + ty * GTM + i;
        __half* dst = g_A3a + (size_t)m * 3072 + n0 + tx * GTN;
        __half2 p1[4], p2[4], p3[4];
        #pragma unroll
        for (int q = 0; q < 4; q++) {
            float a = acc[i][2*q]   + bv[2*q];
            float b = acc[i][2*q+1] + bv[2*q+1];
            float a2 = a * a, b2 = b * b;
            p1[q] = __half2(__float2half_rn(a),     __float2half_rn(b));
            p2[q] = __half2(__float2half_rn(a2),    __float2half_rn(b2));
            p3[q] = __half2(__float2half_rn(a2*a),  __float2half_rn(b2*b));
        }
        *reinterpret_cast<uint4*>(dst)        = *reinterpret_cast<uint4*>(p1);
        *reinterpret_cast<uint4*>(dst + 1024) = *reinterpret_cast<uint4*>(p2);
        *reinterpret_cast<uint4*>(dst + 2048) = *reinterpret_cast<uint4*>(p3);
    }
}

// ---------------- LN + exact GELU + fp16 power split ----------------
__device__ __forceinline__ float block_reduce_sum(float v, float* red, int t) {
    red[t] = v; __syncthreads();
    #pragma unroll
    for (int st = 128; st > 0; st >>= 1) {
        if (t < st) red[t] += red[t + st];
        __syncthreads();
    }
    float r = red[0];
    __syncthreads();
    return r;
}

__global__ void ln_gelu_split_kernel(const float* __restrict__ g, const float* __restrict__ beta) {
    __shared__ float red[256];
    int t = threadIdx.x;
    const float* p = g_h1 + (size_t)blockIdx.x * HID;
    float4 v4 = *reinterpret_cast<const float4*>(p + t * 4);
    float v[4] = {v4.x, v4.y, v4.z, v4.w};
    float s = v[0] + v[1] + v[2] + v[3];
    float mu = block_reduce_sum(s, red, t) * (1.f / HID);
    float s2 = 0.f;
    #pragma unroll
    for (int i = 0; i < 4; i++) { float d = v[i] - mu; s2 += d * d; }
    float rstd = rsqrtf(block_reduce_sum(s2, red, t) * (1.f / HID) + EPS);
    const float4 gg = *reinterpret_cast<const float4*>(g + t * 4);
    const float4 bb = *reinterpret_cast<const float4*>(beta + t * 4);
    float y[4];
    y[0] = (v[0] - mu) * rstd * gg.x + bb.x;
    y[1] = (v[1] - mu) * rstd * gg.y + bb.y;
    y[2] = (v[2] - mu) * rstd * gg.z + bb.z;
    y[3] = (v[3] - mu) * rstd * gg.w + bb.w;
    float p1[4], p2[4], p3[4];
    #pragma unroll
    for (int i = 0; i < 4; i++) {
        float yy = y[i];
        yy = 0.5f * yy * (1.f + erff(yy * 0.70710678118654752f));
        p1[i] = yy; p2[i] = yy * yy; p3[i] = p2[i] * yy;
    }
    __half* Ap = g_A3b + (size_t)blockIdx.x * 3072 + t * 4;
    #pragma unroll
    for (int o = 0; o < 3; o++) {
        const float* pp = (o == 0) ? p1 : (o == 1) ? p2 : p3;
        __half2 h2[2];
        h2[0] = __half2(__float2half_rn(pp[0]), __float2half_rn(pp[1]));
        h2[1] = __half2(__float2half_rn(pp[2]), __float2half_rn(pp[3]));
        *reinterpret_cast<uint2*>(Ap + o * 1024) = *reinterpret_cast<uint2*>(h2);
    }
}

// ---------------- fused KAN GEMM via fp16 mma.sync ----------------
// smem rows are 32B (KC=16): 2 chunks of 16B; swizzle: chunk ^= (row>>2)&1
__device__ __forceinline__ void load_stage_kan(const __half* A3, const __half* B3,
                                               int N, int m0, int n0, int kt,
                                               uint32_t bufA, uint32_t bufB, int tid) {
    int k0 = kt * KC;
    #pragma unroll
    for (int i = 0; i < 3; i++) {            // A: 3 planes * 128 rows * 2 chunks = 768
        int id = tid + i * 256;
        int c = id & 1;
        int m = (id >> 1) & 127;
        int pl = id >> 8;
        const void* gp = (const void*)(A3 + (size_t)(m0 + m) * 3072 + pl * 1024 + k0 + c * 8);
        uint32_t sp = bufA + pl * 4096 + m * 32 + ((uint32_t)(c ^ ((m >> 2) & 1)) << 4);
        asm volatile("cp.async.cg.shared.global [%0], [%1], 16;" :: "r"(sp), "l"(gp));
    }
    #pragma unroll
    for (int i = 0; i < 3; i++) {            // B: 3 planes * 128 rows * 2 chunks = 768
        int id = tid + i * 256;
        int c = id & 1;
        int n = (id >> 1) & 127;
        int pl = id >> 8;
        const void* gp = (const void*)(B3 + (size_t)pl * N * 1024 + (size_t)(n0 + n) * 1024 + k0 + c * 8);
        uint32_t sp = bufB + pl * 4096 + n * 32 + ((uint32_t)(c ^ ((n >> 2) & 1)) << 4);
        asm volatile("cp.async.cg.shared.global [%0], [%1], 16;" :: "r"(sp), "l"(gp));
    }
}

template<int STAGE>
__global__ void __launch_bounds__(256, 2) gemm_kan_mma() {
    const int N      = (STAGE == 1) ? HID : OUTC;
    const __half* A3 = (STAGE == 1) ? g_A3a : g_A3b;
    const __half* B3 = (STAGE == 1) ? g_B3a : g_B3b;
    const float* c0v = (STAGE == 1) ? g_c01 : g_c02;
    float* C         = (STAGE == 1) ? g_h1 : g_h2;

    extern __shared__ char smem[];
    uint32_t sb = smem_u32(smem);
    int tid = threadIdx.x, lane = tid & 31, w = tid >> 5;
    int wm = w >> 1, wn = w & 1;              // warp grid 4(M) x 2(N); warp tile 32x64
    int m0 = blockIdx.y * 128, n0 = blockIdx.x * 128;

    float acc[2][8][4] = {};

    int hiA = lane >> 4;
    int hiB = (lane >> 3) & 1;
    uint32_t aOff[2]; int aSw[2];
    uint32_t bOff[8]; int bSw[8];
    #pragma unroll
    for (int s = 0; s < 2; s++) {
        int r = wm * 32 + s * 16 + (lane & 15);
        aOff[s] = (uint32_t)r * 32; aSw[s] = (r >> 2) & 1;
    }
    #pragma unroll
    for (int t = 0; t < 8; t++) {
        int r = wn * 64 + t * 8 + (lane & 7);
        bOff[t] = (uint32_t)r * 32; bSw[t] = (r >> 2) & 1;
    }

    // prologue: 2 stages in flight
    load_stage_kan(A3, B3, N, m0, n0, 0, sb, sb + A_ST, tid);
    asm volatile("cp.async.commit_group;" ::: "memory");
    load_stage_kan(A3, B3, N, m0, n0, 1, sb + STG, sb + STG + A_ST, tid);
    asm volatile("cp.async.commit_group;" ::: "memory");

    uint32_t bufs[NSTG];
    #pragma unroll
    for (int s = 0; s < NSTG; s++) bufs[s] = sb + (uint32_t)s * STG;

    int slot = 0, lslot = 2;
    for (int kt = 0; kt < NK; kt++) {
        asm volatile("cp.async.wait_group 1;" ::: "memory");
        __syncthreads();

        int j = kt + 2;
        if (j < NK)
            load_stage_kan(A3, B3, N, m0, n0, j, bufs[lslot], bufs[lslot] + A_ST, tid);
        asm volatile("cp.async.commit_group;" ::: "memory");

        uint32_t bufA = bufs[slot];
        uint32_t bufB = bufA + A_ST;

        #pragma unroll
        for (int o = 0; o < 3; o++) {
            uint32_t bh[8][2];
            #pragma unroll
            for (int t = 0; t < 8; t++) {
                uint32_t base = bufB + o * 4096 + bOff[t];
                LDSM_X2(bh[t], base + ((uint32_t)(hiB ^ bSw[t]) << 4));
            }
            #pragma unroll
            for (int s = 0; s < 2; s++) {
                uint32_t ah[4];
                uint32_t base = bufA + o * 4096 + aOff[s];
                LDSM_X4(ah, base + ((uint32_t)(hiA ^ aSw[s]) << 4));
                #pragma unroll
                for (int t = 0; t < 8; t++)
                    MMA16816(acc[s][t], ah, bh[t]);
            }
        }
        slot = (slot + 1 == NSTG) ? 0 : slot + 1;
        lslot = (lslot + 1 == NSTG) ? 0 : lslot + 1;
    }

    // epilogue
    #pragma unroll
    for (int t = 0; t < 8; t++) {
        int col = n0 + wn * 64 + t * 8 + (lane & 3) * 2;
        float c0a = c0v[col], c0b = c0v[col + 1];
        #pragma unroll
        for (int s = 0; s < 2; s++) {
            int r0 = m0 + wm * 32 + s * 16 + (lane >> 2);
            float2 v0 = make_float2(acc[s][t][0] + c0a, acc[s][t][1] + c0b);
            float2 v1 = make_float2(acc[s][t][2] + c0a, acc[s][t][3] + c0b);
            *reinterpret_cast<float2*>(C + (size_t)r0 * N + col) = v0;
            *reinterpret_cast<float2*>(C + (size_t)(r0 + 8) * N + col) = v1;
        }
    }
}

// ---------------- fused LN2 + partial mean over L ----------------
// grid (8 segs, BATCH), block 256 = 8 warps; warp handles 16 rows; lane owns 16 cols
__global__ void ln2_reduce_kernel(const float* __restrict__ g, const float* __restrict__ beta) {
    __shared__ float part[8][OUTC];
    int seg = blockIdx.x, b = blockIdx.y;
    int lane = threadIdx.x & 31, w = threadIdx.x >> 5;
    int colb = lane * 16;

    float gv[16], bv[16];
    #pragma unroll
    for (int q = 0; q < 4; q++) {
        float4 t1 = *reinterpret_cast<const float4*>(g + colb + q * 4);
        float4 t2 = *reinterpret_cast<const float4*>(beta + colb + q * 4);
        gv[q*4+0]=t1.x; gv[q*4+1]=t1.y; gv[q*4+2]=t1.z; gv[q*4+3]=t1.w;
        bv[q*4+0]=t2.x; bv[q*4+1]=t2.y; bv[q*4+2]=t2.z; bv[q*4+3]=t2.w;
    }
    float acc[16];
    #pragma unroll
    for (int j = 0; j < 16; j++) acc[j] = 0.f;

    for (int i = 0; i < 16; i++) {
        int l = seg * 128 + w * 16 + i;
        const float* row = g_h2 + ((size_t)b * LEN + l) * OUTC + colb;
        float v[16];
        float s = 0.f;
        #pragma unroll
        for (int q = 0; q < 4; q++) {
            float4 t = *reinterpret_cast<const float4*>(row + q * 4);
            v[q*4+0]=t.x; v[q*4+1]=t.y; v[q*4+2]=t.z; v[q*4+3]=t.w;
            s += t.x + t.y + t.z + t.w;
        }
        #pragma unroll
        for (int st = 16; st > 0; st >>= 1) s += __shfl_xor_sync(0xFFFFFFFF, s, st);
        float mu = s * (1.f / OUTC);
        float s2 = 0.f;
        #pragma unroll
        for (int j = 0; j < 16; j++) { float d = v[j] - mu; s2 += d * d; }
        #pragma unroll
        for (int st = 16; st > 0; st >>= 1) s2 += __shfl_xor_sync(0xFFFFFFFF, s2, st);
        float rstd = rsqrtf(s2 * (1.f / OUTC) + EPS);
        #pragma unroll
        for (int j = 0; j < 16; j++)
            acc[j] += (v[j] - mu) * rstd * gv[j] + bv[j];
    }
    #pragma unroll
    for (int j = 0; j < 16; j++) part[w][colb + j] = acc[j];
    __syncthreads();
    int col = threadIdx.x;                      // 256 threads, 2 cols each
    #pragma unroll
    for (int q = 0; q < 2; q++) {
        int cc = col + q * 256;
        float s = 0.f;
        #pragma unroll
        for (int ww = 0; ww < 8; ww++) s += part[ww][cc];
        g_part[((size_t)b * 8 + seg) * OUTC + cc] = s;
    }
}

__global__ void reduce2_kernel(float* __restrict__ out) {
    int b = blockIdx.x, o = threadIdx.x;
    const float* p = g_part + (size_t)b * 8 * OUTC + o;
    float s = 0.f;
    #pragma unroll
    for (int seg = 0; seg < 8; seg++) s += p[(size_t)seg * OUTC];
    out[b * OUTC + o] = s * (1.f / LEN);
}

// ---------------- launch ----------------
extern "C" void kernel_launch(void* const* d_in, const int* in_sizes, int n_in,
                              void* d_out, int out_size) {
    const float* x       = (const float*)d_in[0];
    const float* W_in    = (const float*)d_in[1];
    const float* b_in    = (const float*)d_in[2];
    const float* coeffs1 = (const float*)d_in[3];
    const float* bias1   = (const float*)d_in[4];
    const float* g1      = (const float*)d_in[5];
    const float* beta1   = (const float*)d_in[6];
    const float* coeffs2 = (const float*)d_in[7];
    const float* bias2   = (const float*)d_in[8];
    const float* g2      = (const float*)d_in[9];
    const float* beta2   = (const float*)d_in[10];
    float* out = (float*)d_out;

    cudaFuncSetAttribute(gemm_kan_mma<1>, cudaFuncAttributeMaxDynamicSharedMemorySize, SMEM_GEMM);
    cudaFuncSetAttribute(gemm_kan_mma<2>, cudaFuncAttributeMaxDynamicSharedMemorySize, SMEM_GEMM);

    repackB_kernel<1><<<HID, 256>>>(coeffs1, bias1);
    repackB_kernel<2><<<OUTC, 256>>>(coeffs2, bias2);

    gemm_proj_kernel<<<dim3(HID / GBN, MTOT / GBM), NTHR>>>(x, W_in, b_in);
    gemm_kan_mma<1><<<dim3(HID / 128, MTOT / 128), 256, SMEM_GEMM>>>();
    ln_gelu_split_kernel<<<MTOT, 256>>>(g1, beta1);
    gemm_kan_mma<2><<<dim3(OUTC / 128, MTOT / 128), 256, SMEM_GEMM>>>();
    ln2_reduce_kernel<<<dim3(8, BATCH), 256>>>(g2, beta2);
    reduce2_kernel<<<BATCH, OUTC>>>(out);
}

// round 9
// speedup vs baseline: 1.2338x; 1.2338x over previous
#include <cuda_runtime.h>
#include <cuda_fp16.h>
#include <cstdint>
#include <math.h>

#define BATCH 16
#define CIN   64
#define LEN   1024
#define HID   1024
#define OUTC  512
#define EPS   1e-5f
#define MTOT  (BATCH*LEN)   // 16384

// GEMM tiling: CTA 128x128, KC=32, 2-stage double buffer, 2 CTAs/SM (R7 skeleton)
#define KC     32
#define NK     (HID/KC)      // 32
#define A_ST   24576         // 3 A planes * 128 rows * 64B
#define B_ST   24576
#define STG    (A_ST + B_ST) // 49152
#define SMEM_GEMM (2*STG)    // 98304

// fp32 SIMT proj tile params
#define GBM 128
#define GBN 128
#define GBK 16
#define GTM 8
#define GTN 8
#define NTHR 256

// ---------------- scratch ----------------
__device__ __align__(16)  float g_h1[MTOT*HID];
__device__ __align__(16)  float g_h2[MTOT*OUTC];
__device__ __align__(128) __half g_A3a[(size_t)MTOT*3072];   // [m][order(3)][k]
__device__ __align__(128) __half g_A3b[(size_t)MTOT*3072];
__device__ __align__(128) __half g_B3a[(size_t)3*HID*1024];  // [order][n][k]
__device__ __align__(128) __half g_B3b[(size_t)3*OUTC*1024];
__device__ float g_c01[HID];
__device__ float g_c02[OUTC];
__device__ float g_part[BATCH*8*OUTC];

// ---------------- helpers ----------------
__device__ __forceinline__ uint32_t smem_u32(const void* p) {
    uint32_t a;
    asm("{ .reg .u64 t; cvta.to.shared.u64 t, %1; cvt.u32.u64 %0, t; }" : "=r"(a) : "l"(p));
    return a;
}

#define LDSM_X4(r, addr) \
    asm volatile("ldmatrix.sync.aligned.m8n8.x4.shared.b16 {%0,%1,%2,%3}, [%4];" \
        : "=r"((r)[0]), "=r"((r)[1]), "=r"((r)[2]), "=r"((r)[3]) : "r"(addr))
#define MMA16816(d, a, b) \
    asm volatile("mma.sync.aligned.m16n8k16.row.col.f32.f16.f16.f32 " \
        "{%0,%1,%2,%3}, {%4,%5,%6,%7}, {%8,%9}, {%0,%1,%2,%3};" \
        : "+f"((d)[0]), "+f"((d)[1]), "+f"((d)[2]), "+f"((d)[3]) \
        : "r"((a)[0]), "r"((a)[1]), "r"((a)[2]), "r"((a)[3]), "r"((b)[0]), "r"((b)[1]))

// ---------------- B repack (single fp16 plane per order) + c0 ----------------
template<int STAGE>
__global__ void repackB_kernel(const float* __restrict__ coeffs, const float* __restrict__ bias) {
    const int N = (STAGE == 1) ? HID : OUTC;
    __half* B3 = (STAGE == 1) ? g_B3a : g_B3b;
    float* c0  = (STAGE == 1) ? g_c01 : g_c02;
    int o = blockIdx.x;
    __shared__ float red[256];
    float s = 0.f;
    #pragma unroll
    for (int it = 0; it < 4; it++) {
        int c = threadIdx.x + it * 256;
        float4 v = *reinterpret_cast<const float4*>(coeffs + ((size_t)o * HID + c) * 4);
        s += v.x;
        size_t base = (size_t)o * 1024 + c;
        size_t ps = (size_t)N * 1024;
        B3[0*ps + base] = __float2half_rn(v.y);
        B3[1*ps + base] = __float2half_rn(v.z);
        B3[2*ps + base] = __float2half_rn(v.w);
    }
    red[threadIdx.x] = s; __syncthreads();
    #pragma unroll
    for (int st = 128; st > 0; st >>= 1) {
        if (threadIdx.x < st) red[threadIdx.x] += red[threadIdx.x + st];
        __syncthreads();
    }
    if (threadIdx.x == 0) c0[o] = red[0] + bias[o];
}

// ---------------- projection GEMM (fp32 SIMT) + fused power split to fp16 ----------------
__global__ void gemm_proj_kernel(const float* __restrict__ x, const float* __restrict__ W,
                                 const float* __restrict__ bias) {
    __shared__ float As[GBK][GBM];
    __shared__ float Bs[GBK][GBN];
    const int m0 = blockIdx.y * GBM, n0 = blockIdx.x * GBN;
    const int tid = threadIdx.x;
    const int tx = tid & 15, ty = tid >> 4;
    float acc[GTM][GTN] = {};
    for (int kt = 0; kt < CIN; kt += GBK) {
        #pragma unroll
        for (int ii = 0; ii < 8; ii++) {
            int idx = tid + ii * NTHR;
            int mm = idx & (GBM - 1);
            int kk = idx >> 7;
            int m = m0 + mm;
            As[kk][mm] = x[((size_t)(m >> 10) * CIN + (kt + kk)) * LEN + (m & 1023)];
        }
        #pragma unroll
        for (int ii = 0; ii < 8; ii++) {
            int idx = tid + ii * NTHR;
            int nn = idx & (GBN - 1);
            int kk = idx >> 7;
            Bs[kk][nn] = W[(size_t)(kt + kk) * HID + n0 + nn];
        }
        __syncthreads();
        #pragma unroll
        for (int kk = 0; kk < GBK; kk++) {
            float a[GTM], bb[GTN];
            #pragma unroll
            for (int i = 0; i < GTM; i++) a[i] = As[kk][ty * GTM + i];
            #pragma unroll
            for (int j = 0; j < GTN; j++) bb[j] = Bs[kk][tx * GTN + j];
            #pragma unroll
            for (int i = 0; i < GTM; i++)
                #pragma unroll
                for (int j = 0; j < GTN; j++)
                    acc[i][j] = fmaf(a[i], bb[j], acc[i][j]);
        }
        __syncthreads();
    }
    float bv[GTN];
    #pragma unroll
    for (int j = 0; j < GTN; j++) bv[j] = bias[n0 + tx * GTN + j];
    #pragma unroll
    for (int i = 0; i < GTM; i++) {
        int m = m0 + ty * GTM + i;
        __half* dst = g_A3a + (size_t)m * 3072 + n0 + tx * GTN;
        __half2 p1[4], p2[4], p3[4];
        #pragma unroll
        for (int q = 0; q < 4; q++) {
            float a = acc[i][2*q]   + bv[2*q];
            float b = acc[i][2*q+1] + bv[2*q+1];
            float a2 = a * a, b2 = b * b;
            p1[q] = __half2(__float2half_rn(a),     __float2half_rn(b));
            p2[q] = __half2(__float2half_rn(a2),    __float2half_rn(b2));
            p3[q] = __half2(__float2half_rn(a2*a),  __float2half_rn(b2*b));
        }
        *reinterpret_cast<uint4*>(dst)        = *reinterpret_cast<uint4*>(p1);
        *reinterpret_cast<uint4*>(dst + 1024) = *reinterpret_cast<uint4*>(p2);
        *reinterpret_cast<uint4*>(dst + 2048) = *reinterpret_cast<uint4*>(p3);
    }
}

// ---------------- LN + exact GELU + fp16 power split ----------------
__device__ __forceinline__ float block_reduce_sum(float v, float* red, int t) {
    red[t] = v; __syncthreads();
    #pragma unroll
    for (int st = 128; st > 0; st >>= 1) {
        if (t < st) red[t] += red[t + st];
        __syncthreads();
    }
    float r = red[0];
    __syncthreads();
    return r;
}

__global__ void ln_gelu_split_kernel(const float* __restrict__ g, const float* __restrict__ beta) {
    __shared__ float red[256];
    int t = threadIdx.x;
    const float* p = g_h1 + (size_t)blockIdx.x * HID;
    float4 v4 = *reinterpret_cast<const float4*>(p + t * 4);
    float v[4] = {v4.x, v4.y, v4.z, v4.w};
    float s = v[0] + v[1] + v[2] + v[3];
    float mu = block_reduce_sum(s, red, t) * (1.f / HID);
    float s2 = 0.f;
    #pragma unroll
    for (int i = 0; i < 4; i++) { float d = v[i] - mu; s2 += d * d; }
    float rstd = rsqrtf(block_reduce_sum(s2, red, t) * (1.f / HID) + EPS);
    const float4 gg = *reinterpret_cast<const float4*>(g + t * 4);
    const float4 bb = *reinterpret_cast<const float4*>(beta + t * 4);
    float y[4];
    y[0] = (v[0] - mu) * rstd * gg.x + bb.x;
    y[1] = (v[1] - mu) * rstd * gg.y + bb.y;
    y[2] = (v[2] - mu) * rstd * gg.z + bb.z;
    y[3] = (v[3] - mu) * rstd * gg.w + bb.w;
    float p1[4], p2[4], p3[4];
    #pragma unroll
    for (int i = 0; i < 4; i++) {
        float yy = y[i];
        yy = 0.5f * yy * (1.f + erff(yy * 0.70710678118654752f));
        p1[i] = yy; p2[i] = yy * yy; p3[i] = p2[i] * yy;
    }
    __half* Ap = g_A3b + (size_t)blockIdx.x * 3072 + t * 4;
    #pragma unroll
    for (int o = 0; o < 3; o++) {
        const float* pp = (o == 0) ? p1 : (o == 1) ? p2 : p3;
        __half2 h2[2];
        h2[0] = __half2(__float2half_rn(pp[0]), __float2half_rn(pp[1]));
        h2[1] = __half2(__float2half_rn(pp[2]), __float2half_rn(pp[3]));
        *reinterpret_cast<uint2*>(Ap + o * 1024) = *reinterpret_cast<uint2*>(h2);
    }
}

// ---------------- fused KAN GEMM via fp16 mma.sync ----------------
// smem rows are 64B (KC=32): 4 chunks of 16B; swizzle: chunk ^= (row>>1)&3
__device__ __forceinline__ void load_stage_kan(const __half* A3, const __half* B3,
                                               int N, int m0, int n0, int kt,
                                               uint32_t bufA, uint32_t bufB, int tid) {
    int k0 = kt * KC;
    #pragma unroll
    for (int i = 0; i < 6; i++) {            // A: 3 planes * 128 rows * 4 chunks = 1536
        int id = tid + i * 256;
        int c = id & 3;
        int m = (id >> 2) & 127;
        int pl = id >> 9;
        const void* gp = (const void*)(A3 + (size_t)(m0 + m) * 3072 + pl * 1024 + k0 + c * 8);
        uint32_t sp = bufA + pl * 8192 + m * 64 + ((uint32_t)(c ^ ((m >> 1) & 3)) << 4);
        asm volatile("cp.async.cg.shared.global [%0], [%1], 16;" :: "r"(sp), "l"(gp));
    }
    #pragma unroll
    for (int i = 0; i < 6; i++) {            // B: 3 planes * 128 rows * 4 chunks = 1536
        int id = tid + i * 256;
        int c = id & 3;
        int n = (id >> 2) & 127;
        int pl = id >> 9;
        const void* gp = (const void*)(B3 + (size_t)pl * N * 1024 + (size_t)(n0 + n) * 1024 + k0 + c * 8);
        uint32_t sp = bufB + pl * 8192 + n * 64 + ((uint32_t)(c ^ ((n >> 1) & 3)) << 4);
        asm volatile("cp.async.cg.shared.global [%0], [%1], 16;" :: "r"(sp), "l"(gp));
    }
}

template<int STAGE>
__global__ void __launch_bounds__(256, 2) gemm_kan_mma() {
    const int N      = (STAGE == 1) ? HID : OUTC;
    const __half* A3 = (STAGE == 1) ? g_A3a : g_A3b;
    const __half* B3 = (STAGE == 1) ? g_B3a : g_B3b;
    const float* c0v = (STAGE == 1) ? g_c01 : g_c02;
    float* C         = (STAGE == 1) ? g_h1 : g_h2;

    extern __shared__ char smem[];
    uint32_t sb = smem_u32(smem);
    int tid = threadIdx.x, lane = tid & 31, w = tid >> 5;
    int wm = w >> 1, wn = w & 1;              // warp grid 4(M) x 2(N); warp tile 32x64
    int m0 = blockIdx.y * 128, n0 = blockIdx.x * 128;

    float acc[2][8][4] = {};

    // B: per-(o,t) single X4 — lane supplies row (lane&7) of chunk (lane>>3)
    // of B rows [wn*64 + t*8, +8). Fragment: bq[t] = {kk0.b0, kk0.b1, kk1.b0, kk1.b1}
    uint32_t offB[8];
    {
        int c = lane >> 3;                    // chunk 0..3, fixed per lane
        int rr = lane & 7;
        #pragma unroll
        for (int t = 0; t < 8; t++) {
            int r = wn * 64 + t * 8 + rr;
            offB[t] = (uint32_t)r * 64 + ((uint32_t)(c ^ ((r >> 1) & 3)) << 4);
        }
    }
    // A: per-(o,kk,s) X4 as before (lanes 0-15 chunk kk*2, 16-31 chunk kk*2+1)
    int hiA = lane >> 4;
    uint32_t aOff[2]; int aSw[2];
    #pragma unroll
    for (int s = 0; s < 2; s++) {
        int r = wm * 32 + s * 16 + (lane & 15);
        aOff[s] = (uint32_t)r * 64; aSw[s] = (r >> 1) & 3;
    }

    // prologue: both stages in flight
    load_stage_kan(A3, B3, N, m0, n0, 0, sb, sb + A_ST, tid);
    asm volatile("cp.async.commit_group;" ::: "memory");
    load_stage_kan(A3, B3, N, m0, n0, 1, sb + STG, sb + STG + A_ST, tid);
    asm volatile("cp.async.commit_group;" ::: "memory");

    for (int kt = 0; kt < NK; kt++) {
        asm volatile("cp.async.wait_group 1;" ::: "memory");
        __syncthreads();

        uint32_t bufA = sb + (uint32_t)(kt & 1) * STG;
        uint32_t bufB = bufA + A_ST;

        #pragma unroll
        for (int o = 0; o < 3; o++) {
            uint32_t bq[8][4];
            #pragma unroll
            for (int t = 0; t < 8; t++)
                LDSM_X4(bq[t], bufB + o * 8192 + offB[t]);
            #pragma unroll
            for (int kk = 0; kk < 2; kk++) {
                #pragma unroll
                for (int s = 0; s < 2; s++) {
                    uint32_t ah[4];
                    uint32_t base = bufA + o * 8192 + aOff[s];
                    LDSM_X4(ah, base + ((uint32_t)((kk * 2 + hiA) ^ aSw[s]) << 4));
                    #pragma unroll
                    for (int t = 0; t < 8; t++)
                        MMA16816(acc[s][t], ah, &bq[t][kk * 2]);
                }
            }
        }
        __syncthreads();
        int j = kt + 2;
        if (j < NK)
            load_stage_kan(A3, B3, N, m0, n0, j, bufA, bufB, tid);
        asm volatile("cp.async.commit_group;" ::: "memory");
    }

    // epilogue
    #pragma unroll
    for (int t = 0; t < 8; t++) {
        int col = n0 + wn * 64 + t * 8 + (lane & 3) * 2;
        float c0a = c0v[col], c0b = c0v[col + 1];
        #pragma unroll
        for (int s = 0; s < 2; s++) {
            int r0 = m0 + wm * 32 + s * 16 + (lane >> 2);
            float2 v0 = make_float2(acc[s][t][0] + c0a, acc[s][t][1] + c0b);
            float2 v1 = make_float2(acc[s][t][2] + c0a, acc[s][t][3] + c0b);
            *reinterpret_cast<float2*>(C + (size_t)r0 * N + col) = v0;
            *reinterpret_cast<float2*>(C + (size_t)(r0 + 8) * N + col) = v1;
        }
    }
}

// ---------------- fused LN2 + partial mean over L ----------------
// grid (8 segs, BATCH), block 256 = 8 warps; warp handles 16 rows; lane owns 16 cols
__global__ void ln2_reduce_kernel(const float* __restrict__ g, const float* __restrict__ beta) {
    __shared__ float part[8][OUTC];
    int seg = blockIdx.x, b = blockIdx.y;
    int lane = threadIdx.x & 31, w = threadIdx.x >> 5;
    int colb = lane * 16;

    float gv[16], bv[16];
    #pragma unroll
    for (int q = 0; q < 4; q++) {
        float4 t1 = *reinterpret_cast<const float4*>(g + colb + q * 4);
        float4 t2 = *reinterpret_cast<const float4*>(beta + colb + q * 4);
        gv[q*4+0]=t1.x; gv[q*4+1]=t1.y; gv[q*4+2]=t1.z; gv[q*4+3]=t1.w;
        bv[q*4+0]=t2.x; bv[q*4+1]=t2.y; bv[q*4+2]=t2.z; bv[q*4+3]=t2.w;
    }
    float acc[16];
    #pragma unroll
    for (int j = 0; j < 16; j++) acc[j] = 0.f;

    for (int i = 0; i < 16; i++) {
        int l = seg * 128 + w * 16 + i;
        const float* row = g_h2 + ((size_t)b * LEN + l) * OUTC + colb;
        float v[16];
        float s = 0.f;
        #pragma unroll
        for (int q = 0; q < 4; q++) {
            float4 t = *reinterpret_cast<const float4*>(row + q * 4);
            v[q*4+0]=t.x; v[q*4+1]=t.y; v[q*4+2]=t.z; v[q*4+3]=t.w;
            s += t.x + t.y + t.z + t.w;
        }
        #pragma unroll
        for (int st = 16; st > 0; st >>= 1) s += __shfl_xor_sync(0xFFFFFFFF, s, st);
        float mu = s * (1.f / OUTC);
        float s2 = 0.f;
        #pragma unroll
        for (int j = 0; j < 16; j++) { float d = v[j] - mu; s2 += d * d; }
        #pragma unroll
        for (int st = 16; st > 0; st >>= 1) s2 += __shfl_xor_sync(0xFFFFFFFF, s2, st);
        float rstd = rsqrtf(s2 * (1.f / OUTC) + EPS);
        #pragma unroll
        for (int j = 0; j < 16; j++)
            acc[j] += (v[j] - mu) * rstd * gv[j] + bv[j];
    }
    #pragma unroll
    for (int j = 0; j < 16; j++) part[w][colb + j] = acc[j];
    __syncthreads();
    int col = threadIdx.x;                      // 256 threads, 2 cols each
    #pragma unroll
    for (int q = 0; q < 2; q++) {
        int cc = col + q * 256;
        float s = 0.f;
        #pragma unroll
        for (int ww = 0; ww < 8; ww++) s += part[ww][cc];
        g_part[((size_t)b * 8 + seg) * OUTC + cc] = s;
    }
}

__global__ void reduce2_kernel(float* __restrict__ out) {
    int b = blockIdx.x, o = threadIdx.x;
    const float* p = g_part + (size_t)b * 8 * OUTC + o;
    float s = 0.f;
    #pragma unroll
    for (int seg = 0; seg < 8; seg++) s += p[(size_t)seg * OUTC];
    out[b * OUTC + o] = s * (1.f / LEN);
}

// ---------------- launch ----------------
extern "C" void kernel_launch(void* const* d_in, const int* in_sizes, int n_in,
                              void* d_out, int out_size) {
    const float* x       = (const float*)d_in[0];
    const float* W_in    = (const float*)d_in[1];
    const float* b_in    = (const float*)d_in[2];
    const float* coeffs1 = (const float*)d_in[3];
    const float* bias1   = (const float*)d_in[4];
    const float* g1      = (const float*)d_in[5];
    const float* beta1   = (const float*)d_in[6];
    const float* coeffs2 = (const float*)d_in[7];
    const float* bias2   = (const float*)d_in[8];
    const float* g2      = (const float*)d_in[9];
    const float* beta2   = (const float*)d_in[10];
    float* out = (float*)d_out;

    cudaFuncSetAttribute(gemm_kan_mma<1>, cudaFuncAttributeMaxDynamicSharedMemorySize, SMEM_GEMM);
    cudaFuncSetAttribute(gemm_kan_mma<2>, cudaFuncAttributeMaxDynamicSharedMemorySize, SMEM_GEMM);

    repackB_kernel<1><<<HID, 256>>>(coeffs1, bias1);
    repackB_kernel<2><<<OUTC, 256>>>(coeffs2, bias2);

    gemm_proj_kernel<<<dim3(HID / GBN, MTOT / GBM), NTHR>>>(x, W_in, b_in);
    gemm_kan_mma<1><<<dim3(HID / 128, MTOT / 128), 256, SMEM_GEMM>>>();
    ln_gelu_split_kernel<<<MTOT, 256>>>(g1, beta1);
    gemm_kan_mma<2><<<dim3(OUTC / 128, MTOT / 128), 256, SMEM_GEMM>>>();
    ln2_reduce_kernel<<<dim3(8, BATCH), 256>>>(g2, beta2);
    reduce2_kernel<<<BATCH, OUTC>>>(out);
}